// round 4
// baseline (speedup 1.0000x reference)
#include <cuda_runtime.h>
#include <cuda_fp16.h>

#define H 512
#define W 512
#define NP 24                 // 8*3 planes
#define KWIN 10
#define WXROWS 502
#define WXCOLS 503
#define WYROWS 503
#define WYCOLS 502
#define LWIN (WXROWS*WXCOLS)  // 252506 (== WYROWS*WYCOLS)
#define NBANDS 12
#define BAND 43               // 12*43 = 516 >= 512

// scratch: packed (numerator = Wl+Wr, denominator = Wi) window sums
__device__ __half2 g_X[NP * LWIN];   // x-grad windows, [p][502][503]
__device__ __half2 g_Y[NP * LWIN];   // y-grad windows, [p][503][502]
__device__ double  g_acc[3];         // gx_sum, gy_sum, norm_sum

__global__ void zero_acc_kernel() {
    if (threadIdx.x < 3) g_acc[threadIdx.x] = 0.0;
}

__device__ __forceinline__ float warp_red(float v) {
    #pragma unroll
    for (int o = 16; o; o >>= 1) v += __shfl_down_sync(0xffffffffu, v, o);
    return v;
}

// smem layout (bytes):
//  ringX: 10*512 half2  = 20480
//  ringY: 10*512 half2  = 20480
//  VxS:   512 half2     =  2048
//  VyS:   512 half2     =  2048
//  rowl/rowr/rowi: 512f =  6144
//  red:   64f           =   256
#define SMEM_BYTES (20480*2 + 2048*2 + 2048*3 + 256)

__global__ void __launch_bounds__(512, 2) win_kernel(
        const float* __restrict__ Al,
        const float* __restrict__ Ar,
        const float* __restrict__ Ai) {
    extern __shared__ unsigned char smraw[];
    __half2* ringX = (__half2*)smraw;            // [10][512]
    __half2* ringY = ringX + 10 * 512;           // [10][512]
    __half2* VxS   = ringY + 10 * 512;           // [512]
    __half2* VyS   = VxS + 512;                  // [512]
    float*   rowl  = (float*)(VyS + 512);        // [512]
    float*   rowr  = rowl + 512;
    float*   rowi  = rowr + 512;
    float*   red   = rowi + 512;                 // [64]

    const int c  = threadIdx.x;
    const int p  = blockIdx.y;
    const int R0 = blockIdx.x * BAND;
    const int R1 = min(R0 + BAND, H);
    const int rend = min(R1 + 9, H - 1);

    const __half2 hz = __floats2half2_rn(0.f, 0.f);
    #pragma unroll
    for (int k = c; k < 10 * 512; k += 512) { ringX[k] = hz; ringY[k] = hz; }
    VxS[c] = hz; VyS[c] = hz;

    const size_t pb = (size_t)p * H * W;
    const float* Bl = Al + pb;
    const float* Br = Ar + pb;
    const float* Bi = Ai + pb;

    float Vxn = 0.f, Vxd = 0.f, Vyn = 0.f, Vyd = 0.f;
    float prevl = 0.f, prevr = 0.f, previ = 0.f;
    float gxacc = 0.f, gyacc = 0.f;
    __syncthreads();

    for (int r = R0; r <= rend; ++r) {
        const float cl = Bl[r * W + c];
        const float cr = Br[r * W + c];
        const float ci = Bi[r * W + c];
        rowl[c] = cl; rowr[c] = cr; rowi[c] = ci;
        __syncthreads();   // rowbuf visible, prev iter's V-reads done

        // ---- gy row r (within-row diff) ----
        float uy = 0.f, dy = 0.f;
        if (c < W - 1) {
            float gl = rowl[c + 1] - cl;
            float gr = rowr[c + 1] - cr;
            float gi = rowi[c + 1] - ci;
            uy = fabsf(gl) + fabsf(gr);
            dy = fabsf(gi);
            if (r < R1) gyacc += fabsf(gl + gr - gi);
        }
        {
            int slot = ((r - R0) % 10) * 512 + c;
            __half2 h = __floats2half2_rn(uy, dy);
            __half2 old = ringY[slot];
            ringY[slot] = h;
            float2 hf = __half22float2(h), of = __half22float2(old);
            Vyn += hf.x - of.x;  Vyd += hf.y - of.y;
            VyS[c] = __floats2half2_rn(Vyn, Vyd);
        }
        // ---- gx row g = r-1 (cross-row diff) ----
        if (r > R0) {
            float gl = cl - prevl;
            float gr = cr - prevr;
            float gi = ci - previ;
            float ux = fabsf(gl) + fabsf(gr);
            float dx = fabsf(gi);
            int g = r - 1;
            if (g < R1) gxacc += fabsf(gl + gr - gi);
            int slot = ((g - R0) % 10) * 512 + c;
            __half2 h = __floats2half2_rn(ux, dx);
            __half2 old = ringX[slot];
            ringX[slot] = h;
            float2 hf = __half22float2(h), of = __half22float2(old);
            Vxn += hf.x - of.x;  Vxd += hf.y - of.y;
            VxS[c] = __floats2half2_rn(Vxn, Vxd);
        }
        prevl = cl; prevr = cr; previ = ci;
        __syncthreads();   // V arrays published

        // ---- horizontal 10-wide box sums ----
        const int ry = r - 9;
        if (ry >= R0 && ry < R1 && ry < WYROWS && c < WYCOLS) {
            float sn = 0.f, sd = 0.f;
            #pragma unroll
            for (int d = 0; d < 10; ++d) {
                float2 v = __half22float2(VyS[c + d]);
                sn += v.x; sd += v.y;
            }
            g_Y[p * LWIN + ry * WYCOLS + c] = __floats2half2_rn(sn, sd);
        }
        const int rx = r - 10;
        if (rx >= R0 && rx < R1 && rx < WXROWS && c < WXCOLS) {
            float sn = 0.f, sd = 0.f;
            #pragma unroll
            for (int d = 0; d < 10; ++d) {
                float2 v = __half22float2(VxS[c + d]);
                sn += v.x; sd += v.y;
            }
            g_X[p * LWIN + rx * WXCOLS + c] = __floats2half2_rn(sn, sd);
        }
    }

    // ---- block reduce grad partials ----
    __syncthreads();
    float vx = warp_red(gxacc);
    float vy = warp_red(gyacc);
    int wid = c >> 5, lid = c & 31;
    if (lid == 0) { red[wid] = vx; red[32 + wid] = vy; }
    __syncthreads();
    if (wid == 0) {
        float a = (lid < 16) ? red[lid] : 0.f;
        float b = (lid < 16) ? red[32 + lid] : 0.f;
        a = warp_red(a);
        b = warp_red(b);
        if (lid == 0) {
            atomicAdd(&g_acc[0], (double)a);
            atomicAdd(&g_acc[1], (double)b);
        }
    }
}

__global__ void __launch_bounds__(256) ratio_kernel() {
    const int n = NP * LWIN;
    float acc = 0.f;
    for (int i = blockIdx.x * blockDim.x + threadIdx.x; i < n;
         i += gridDim.x * blockDim.x) {
        float2 x = __half22float2(g_X[i]);
        float2 y = __half22float2(g_Y[i]);
        // ratio = ((Nx+Ny)/100) / ((Dx+Dy)/100 + EPS) = (Nx+Ny)/(Dx+Dy+1e-4)
        acc += __fdividef(x.x + y.x, x.y + y.y + 1e-4f);
    }
    acc = warp_red(acc);
    __shared__ float red2[8];
    int wid = threadIdx.x >> 5, lid = threadIdx.x & 31;
    if (lid == 0) red2[wid] = acc;
    __syncthreads();
    if (wid == 0) {
        float a = (lid < 8) ? red2[lid] : 0.f;
        a = warp_red(a);
        if (lid == 0) atomicAdd(&g_acc[2], (double)a);
    }
}

__global__ void final_kernel(float* __restrict__ out) {
    double norm_loss = g_acc[2] / (double)(NP * LWIN);            // 6,060,144
    double grad_loss = g_acc[0] / 6279168.0 + g_acc[1] / 6279168.0; // 24*511*512
    out[0] = (float)(norm_loss * 1e-4 + grad_loss);
}

extern "C" void kernel_launch(void* const* d_in, const int* in_sizes, int n_in,
                              void* d_out, int out_size) {
    const float* l  = (const float*)d_in[0];
    const float* r  = (const float*)d_in[1];
    const float* ii = (const float*)d_in[2];
    float* out = (float*)d_out;

    cudaFuncSetAttribute(win_kernel,
                         cudaFuncAttributeMaxDynamicSharedMemorySize, SMEM_BYTES);

    zero_acc_kernel<<<1, 32>>>();
    dim3 g1(NBANDS, NP);
    win_kernel<<<g1, 512, SMEM_BYTES>>>(l, r, ii);
    ratio_kernel<<<1184, 256>>>();
    final_kernel<<<1, 1>>>(out);
}

// round 5
// speedup vs baseline: 1.2906x; 1.2906x over previous
#include <cuda_runtime.h>
#include <cuda_fp16.h>

#define H 512
#define W 512
#define NP 24                 // 8*3 planes
#define WXROWS 502
#define WXCOLS 503
#define WYROWS 503
#define WYCOLS 502
#define LWIN (WXROWS*WXCOLS)  // 252506 per plane
#define NBANDS 12
#define BAND 43               // 12*43 = 516 >= 512

__device__ double g_acc[3];   // gx_sum, gy_sum, norm_sum

__global__ void zero_acc_kernel() {
    if (threadIdx.x < 3) g_acc[threadIdx.x] = 0.0;
}

__device__ __forceinline__ float warp_red(float v) {
    #pragma unroll
    for (int o = 16; o; o >>= 1) v += __shfl_down_sync(0xffffffffu, v, o);
    return v;
}

// smem layout:
//  ringX: 10*512 half2 = 20480
//  ringY: 10*512 half2 = 20480
//  VxS:   512 half2    =  2048
//  VyS:   512 half2    =  2048
//  Ybuf:  2*512 half2  =  4096
//  rowl/rowr/rowi      =  6144
//  red:   96f          =   384
#define SMEM_BYTES (20480*2 + 2048*2 + 4096 + 6144 + 384)

__global__ void __launch_bounds__(512, 2) win_kernel(
        const float* __restrict__ Al,
        const float* __restrict__ Ar,
        const float* __restrict__ Ai) {
    extern __shared__ unsigned char smraw[];
    __half2* ringX = (__half2*)smraw;            // [10][512]
    __half2* ringY = ringX + 10 * 512;           // [10][512]
    __half2* VxS   = ringY + 10 * 512;           // [512]
    __half2* VyS   = VxS + 512;                  // [512]
    __half2* Ybuf  = VyS + 512;                  // [2][512] ring of Y window rows
    float*   rowl  = (float*)(Ybuf + 2 * 512);   // [512]
    float*   rowr  = rowl + 512;
    float*   rowi  = rowr + 512;
    float*   red   = rowi + 512;                 // [96]

    const int c  = threadIdx.x;
    const int p  = blockIdx.y;
    const int R0 = blockIdx.x * BAND;
    const int R1 = min(R0 + BAND, H);
    const int rend = min(R1 + 9, H - 1);

    const __half2 hz = __floats2half2_rn(0.f, 0.f);
    #pragma unroll
    for (int k = c; k < 10 * 512; k += 512) { ringX[k] = hz; ringY[k] = hz; }
    VxS[c] = hz; VyS[c] = hz;

    const size_t pb = (size_t)p * H * W;
    const float* Bl = Al + pb;
    const float* Br = Ar + pb;
    const float* Bi = Ai + pb;

    float Vxn = 0.f, Vxd = 0.f, Vyn = 0.f, Vyd = 0.f;
    float prevl = 0.f, prevr = 0.f, previ = 0.f;
    float gxacc = 0.f, gyacc = 0.f, normacc = 0.f;
    float xn_pend = 0.f, xd_pend = 0.f;   // X window box value, consumed next iter
    __syncthreads();

    for (int r = R0; r <= rend; ++r) {
        const float cl = Bl[r * W + c];
        const float cr = Br[r * W + c];
        const float ci = Bi[r * W + c];
        rowl[c] = cl; rowr[c] = cr; rowi[c] = ci;
        __syncthreads();   // (A) rowbuf + prev-iter Ybuf writes visible

        // ---- ratio for pending X window row rxp = r-11 (set last iteration) ----
        {
            const int rxp = r - 11;
            if (rxp >= R0 && rxp < R1 && rxp < WXROWS && c < WXCOLS) {
                int t = rxp + c;
                int ry = rxp, cy = t;
                if (t >= WYCOLS) { ry = rxp + 1; cy = t - WYCOLS; }
                float2 yv = __half22float2(Ybuf[(ry & 1) * 512 + cy]);
                normacc += __fdividef(xn_pend + yv.x, xd_pend + yv.y + 1e-4f);
            }
        }

        // ---- gy row r (within-row diff) ----
        float uy = 0.f, dy = 0.f;
        if (c < W - 1) {
            float gl = rowl[c + 1] - cl;
            float gr = rowr[c + 1] - cr;
            float gi = rowi[c + 1] - ci;
            uy = fabsf(gl) + fabsf(gr);
            dy = fabsf(gi);
            if (r < R1) gyacc += fabsf(gl + gr - gi);
        }
        {
            int slot = ((r - R0) % 10) * 512 + c;
            __half2 h = __floats2half2_rn(uy, dy);
            __half2 old = ringY[slot];
            ringY[slot] = h;
            float2 hf = __half22float2(h), of = __half22float2(old);
            Vyn += hf.x - of.x;  Vyd += hf.y - of.y;
            VyS[c] = __floats2half2_rn(Vyn, Vyd);
        }
        // ---- gx row g = r-1 (cross-row diff) ----
        if (r > R0) {
            float gl = cl - prevl;
            float gr = cr - prevr;
            float gi = ci - previ;
            float ux = fabsf(gl) + fabsf(gr);
            float dx = fabsf(gi);
            int g = r - 1;
            if (g < R1) gxacc += fabsf(gl + gr - gi);
            int slot = ((g - R0) % 10) * 512 + c;
            __half2 h = __floats2half2_rn(ux, dx);
            __half2 old = ringX[slot];
            ringX[slot] = h;
            float2 hf = __half22float2(h), of = __half22float2(old);
            Vxn += hf.x - of.x;  Vxd += hf.y - of.y;
            VxS[c] = __floats2half2_rn(Vxn, Vxd);
        }
        prevl = cl; prevr = cr; previ = ci;
        __syncthreads();   // (B) V arrays published; pending-ratio reads done

        // ---- horizontal 10-wide box sums ----
        const int ry = r - 9;
        if (ry >= R0 && ry <= R1 && ry < WYROWS && c < WYCOLS) {
            float sn = 0.f, sd = 0.f;
            #pragma unroll
            for (int d = 0; d < 10; ++d) {
                float2 v = __half22float2(VyS[c + d]);
                sn += v.x; sd += v.y;
            }
            Ybuf[(ry & 1) * 512 + c] = __floats2half2_rn(sn, sd);
        }
        const int rx = r - 10;
        if (rx >= R0 && rx < R1 && rx < WXROWS && c < WXCOLS) {
            float sn = 0.f, sd = 0.f;
            #pragma unroll
            for (int d = 0; d < 10; ++d) {
                float2 v = __half22float2(VxS[c + d]);
                sn += v.x; sd += v.y;
            }
            xn_pend = sn; xd_pend = sd;   // consumed next iteration / epilogue
        }
    }

    // ---- epilogue: last pending X row (rxp = rend-10) ----
    __syncthreads();
    {
        const int rxp = rend - 10;
        if (rxp >= R0 && rxp < R1 && rxp < WXROWS && c < WXCOLS) {
            int t = rxp + c;
            int ry = rxp, cy = t;
            if (t >= WYCOLS) { ry = rxp + 1; cy = t - WYCOLS; }
            float2 yv = __half22float2(Ybuf[(ry & 1) * 512 + cy]);
            normacc += __fdividef(xn_pend + yv.x, xd_pend + yv.y + 1e-4f);
        }
    }

    // ---- block reduce: gx, gy, norm ----
    __syncthreads();
    float vx = warp_red(gxacc);
    float vy = warp_red(gyacc);
    float vn = warp_red(normacc);
    int wid = c >> 5, lid = c & 31;
    if (lid == 0) { red[wid] = vx; red[32 + wid] = vy; red[64 + wid] = vn; }
    __syncthreads();
    if (wid == 0) {
        float a = (lid < 16) ? red[lid]      : 0.f;
        float b = (lid < 16) ? red[32 + lid] : 0.f;
        float n = (lid < 16) ? red[64 + lid] : 0.f;
        a = warp_red(a);
        b = warp_red(b);
        n = warp_red(n);
        if (lid == 0) {
            atomicAdd(&g_acc[0], (double)a);
            atomicAdd(&g_acc[1], (double)b);
            atomicAdd(&g_acc[2], (double)n);
        }
    }
}

__global__ void final_kernel(float* __restrict__ out) {
    double norm_loss = g_acc[2] / (double)(NP * LWIN);              // 6,060,144
    double grad_loss = g_acc[0] / 6279168.0 + g_acc[1] / 6279168.0; // 24*511*512
    out[0] = (float)(norm_loss * 1e-4 + grad_loss);
}

extern "C" void kernel_launch(void* const* d_in, const int* in_sizes, int n_in,
                              void* d_out, int out_size) {
    const float* l  = (const float*)d_in[0];
    const float* r  = (const float*)d_in[1];
    const float* ii = (const float*)d_in[2];
    float* out = (float*)d_out;

    cudaFuncSetAttribute(win_kernel,
                         cudaFuncAttributeMaxDynamicSharedMemorySize, SMEM_BYTES);

    zero_acc_kernel<<<1, 32>>>();
    dim3 g1(NBANDS, NP);
    win_kernel<<<g1, 512, SMEM_BYTES>>>(l, r, ii);
    final_kernel<<<1, 1>>>(out);
}